// round 17
// baseline (speedup 1.0000x reference)
#include <cuda_runtime.h>

#define D_MODEL 512
static constexpr float INT64_MAX_F = 9.2233720368547758e18f;

// ---------------------------------------------------------------------------
// Shifted-Stirling pieces for t in [1, ~9]:
//   y = t + 4 >= 5, u = t(t+3), d = t(t+1)(t+2)(t+3) = u(u+2)
//   lgamma(t) = stirling(y) - ln d       (ln d merged across the 3 calls)
//   digamma(t) = psi(y) - (2t+3)(2u+2)/d
// __logf (MUFU.LG2) + 2-term series: abs err < 1e-6 on this domain.
// ---------------------------------------------------------------------------
__device__ __forceinline__ void lgd_parts(float t, float& st, float& dg, float& d) {
    const float u = t * (t + 3.0f);
    d = u * (u + 2.0f);
    const float y = t + 4.0f;
    const float ln_y  = __logf(y);
    const float inv_y = __fdividef(1.0f, y);
    const float inv2  = inv_y * inv_y;
    const float r     = (2.0f * t + 3.0f) * (2.0f * u + 2.0f) * __fdividef(1.0f, d);

    st = fmaf(y - 0.5f, ln_y, -y) + 0.918938533204672742f   // 0.5*ln(2*pi)
       + inv_y * (0.0833333333333f - inv2 * 0.00277777777778f);
    dg = ln_y - 0.5f * inv_y
       - inv2 * (0.0833333333333f - inv2 * 0.00833333333333f)
       - r;
}

// ---------------------------------------------------------------------------
// Kernel A: gather + dual dot product (best-measured configuration, frozen).
// One warp handles 4 actors; 16 independent float4 gathers per lane.
// ---------------------------------------------------------------------------
__global__ void __launch_bounds__(256)
cah_gemv_kernel(const float* __restrict__ x,
                const int*   __restrict__ actors,
                const float* __restrict__ w,
                const float* __restrict__ bvec,
                float*       __restrict__ out,
                int n_actors)
{
    const int lane = threadIdx.x & 31;
    const int warp = (blockIdx.x * blockDim.x + threadIdx.x) >> 5;

    const int i0 = warp * 4;
    if (i0 >= n_actors) return;

    float4 w0r[4], w1r[4];
    #pragma unroll
    for (int j = 0; j < 4; j++) {
        int c = j * 128 + lane * 4;
        w0r[j] = *reinterpret_cast<const float4*>(w + c);
        w1r[j] = *reinterpret_cast<const float4*>(w + D_MODEL + c);
    }
    const float b0 = bvec[0];
    const float b1 = bvec[1];

    const float4* xr[4];
    #pragma unroll
    for (int q = 0; q < 4; q++) {
        const int idx = (i0 + q < n_actors) ? (i0 + q) : i0;
        const int row = __ldg(actors + idx);
        xr[q] = reinterpret_cast<const float4*>(x + (size_t)row * D_MODEL);
    }

    float4 v[4][4];
    #pragma unroll
    for (int q = 0; q < 4; q++)
        #pragma unroll
        for (int j = 0; j < 4; j++)
            v[q][j] = __ldg(xr[q] + j * 32 + lane);

    float acc[4][2];
    #pragma unroll
    for (int q = 0; q < 4; q++) {
        float s0 = 0.0f, s1 = 0.0f;
        #pragma unroll
        for (int j = 0; j < 4; j++) {
            s0 = fmaf(v[q][j].x, w0r[j].x, s0); s0 = fmaf(v[q][j].y, w0r[j].y, s0);
            s0 = fmaf(v[q][j].z, w0r[j].z, s0); s0 = fmaf(v[q][j].w, w0r[j].w, s0);
            s1 = fmaf(v[q][j].x, w1r[j].x, s1); s1 = fmaf(v[q][j].y, w1r[j].y, s1);
            s1 = fmaf(v[q][j].z, w1r[j].z, s1); s1 = fmaf(v[q][j].w, w1r[j].w, s1);
        }
        acc[q][0] = s0; acc[q][1] = s1;
    }

    #pragma unroll
    for (int off = 16; off > 0; off >>= 1) {
        #pragma unroll
        for (int q = 0; q < 4; q++) {
            acc[q][0] += __shfl_xor_sync(0xffffffffu, acc[q][0], off);
            acc[q][1] += __shfl_xor_sync(0xffffffffu, acc[q][1], off);
        }
    }

    if (lane == 0) {
        float lg[8];
        #pragma unroll
        for (int q = 0; q < 4; q++) {
            const float z0 = acc[q][0] + b0;
            const float z1 = acc[q][1] + b1;
            lg[2*q]   = fmaf(z0, z0, 1.0f);
            lg[2*q+1] = fmaf(z1, z1, 1.0f);
        }
        float* lbase = out + 3 * (size_t)n_actors + 2 * (size_t)i0;
        if (i0 + 3 < n_actors) {
            *reinterpret_cast<float4*>(lbase)     = make_float4(lg[0], lg[1], lg[2], lg[3]);
            *reinterpret_cast<float4*>(lbase + 4) = make_float4(lg[4], lg[5], lg[6], lg[7]);
        } else {
            for (int q = 0; q < 4 && i0 + q < n_actors; q++) {
                lbase[2*q]   = lg[2*q];
                lbase[2*q+1] = lg[2*q+1];
            }
        }
    }
}

// ---------------------------------------------------------------------------
// Kernel B: PDL epilogue. Launched with programmatic stream serialization:
// the INDEPENDENT preamble (prev load, action compute+store) executes while
// the gemv is still draining; only the logits-dependent part waits on
// cudaGridDependencySynchronize().
// ---------------------------------------------------------------------------
__global__ void __launch_bounds__(256)
cah_epilogue_kernel(const int* __restrict__ prev,
                    float*     __restrict__ out,
                    int n_actors)
{
    const int i = blockIdx.x * blockDim.x + threadIdx.x;

    float action = 0.0f;
    if (i < n_actors) {
        const float pa = (float)__ldg(prev + i);
        action = pa * (1.0f / INT64_MAX_F);
        out[i] = action * INT64_MAX_F;   // action_return: independent of gemv
    }

    // Wait for the gemv grid to complete before touching logits.
    cudaGridDependencySynchronize();

    if (i >= n_actors) return;

    const float2 l = *reinterpret_cast<const float2*>(out + 3 * (size_t)n_actors + 2 * (size_t)i);
    const float a  = l.x;
    const float bb = l.y;

    float st_a, dg_a, d_a;
    float st_b, dg_b, d_b;
    float st_s, dg_s, d_s;
    lgd_parts(a,      st_a, dg_a, d_a);
    lgd_parts(bb,     st_b, dg_b, d_b);
    lgd_parts(a + bb, st_s, dg_s, d_s);

    const float lbeta = st_a + st_b - st_s
                      - __logf(d_a * d_b * __fdividef(1.0f, d_s));

    const float logprob = (a - 1.0f) * __logf(action)
                        - (bb - 1.0f) * action        // == (bb-1)*log1p(-action)
                        - lbeta;

    const float ent = lbeta
                    - (a - 1.0f)  * dg_a
                    - (bb - 1.0f) * dg_b
                    + (a + bb - 2.0f) * dg_s;

    out[(size_t)n_actors + i]     = logprob;
    out[2 * (size_t)n_actors + i] = ent;
}

extern "C" void kernel_launch(void* const* d_in, const int* in_sizes, int n_in,
                              void* d_out, int out_size)
{
    const float* x      = (const float*)d_in[0];
    const int*   actors = (const int*)  d_in[1];
    const float* w      = (const float*)d_in[2];
    const float* bvec   = (const float*)d_in[3];
    const int*   prev   = (const int*)  d_in[4];
    float*       out    = (float*)d_out;

    const int n_actors = in_sizes[1];  // 262144
    const int T = 256;

    const int warpsA  = (n_actors + 3) / 4;
    const int blocksA = (warpsA * 32 + T - 1) / T;
    cah_gemv_kernel<<<blocksA, T>>>(x, actors, w, bvec, out, n_actors);

    // Epilogue with programmatic dependent launch: starts while gemv drains;
    // cudaGridDependencySynchronize() inside gates the dependent half.
    const int blocksB = (n_actors + T - 1) / T;

    cudaLaunchConfig_t cfg = {};
    cfg.gridDim  = dim3((unsigned)blocksB, 1, 1);
    cfg.blockDim = dim3((unsigned)T, 1, 1);
    cfg.dynamicSmemBytes = 0;
    cfg.stream = 0;   // capture (legacy default) stream

    cudaLaunchAttribute attrs[1];
    attrs[0].id = cudaLaunchAttributeProgrammaticStreamSerialization;
    attrs[0].val.programmaticStreamSerializationAllowed = 1;
    cfg.attrs    = attrs;
    cfg.numAttrs = 1;

    cudaLaunchKernelEx(&cfg, cah_epilogue_kernel, prev, out, n_actors);
}